// round 1
// baseline (speedup 1.0000x reference)
#include <cuda_runtime.h>
#include <math.h>

// Problem constants
#define T      4096
#define DH     64
#define NH     4        // n_hashes
#define NB     64       // buckets per hash
#define DM     512
#define BHN    32       // B*H
#define SELF_VAL (-5e4f)

// ---------------- scratch (device globals; no allocation allowed) ----------------
__device__ float g_qk [(size_t)BHN * T * DH];        // merged qk  (bh, t, dh)   32MB
__device__ float g_v  [(size_t)BHN * T * DH];        // merged v                 32MB
__device__ int   g_st [BHN * NH * T];                // sorted original positions 2MB
__device__ float g_o  [(size_t)BHN * NH * T * DH];   // per-round outputs       128MB
__device__ float g_lse[BHN * NH * T];                // per-round logsumexp       2MB
__device__ float g_ctx[(size_t)4 * T * DM];          // combined context (B,T,DM) 32MB

// ---------------- GEMM: C[16384,512] = A[16384,512] @ B[512,512] ----------------
// MODE 0: A=param, write merged -> g_qk
// MODE 1: A=param, write merged -> g_v
// MODE 2: A=g_ctx, write C param (+bias)
template <int MODE>
__global__ void gemm_kernel(const float* __restrict__ A,
                            const float* __restrict__ Bm,
                            const float* __restrict__ bias,
                            float* __restrict__ C)
{
    const int N = 512, K = 512;
    __shared__ float As[16][68];
    __shared__ float Bs[16][68];
    const float* Ap = (MODE == 2) ? g_ctx : A;

    int tx = threadIdx.x & 15, ty = threadIdx.x >> 4;
    int bm = blockIdx.y * 64, bn = blockIdx.x * 64;
    float acc[4][4] = {};

    for (int k0 = 0; k0 < K; k0 += 16) {
        // A tile 64x16 (transposed store)
        {
            int m  = threadIdx.x >> 2;
            int kk = (threadIdx.x & 3) << 2;
            float4 av = *(const float4*)&Ap[(size_t)(bm + m) * K + k0 + kk];
            As[kk + 0][m] = av.x; As[kk + 1][m] = av.y;
            As[kk + 2][m] = av.z; As[kk + 3][m] = av.w;
        }
        // B tile 16x64
        {
            int kb = threadIdx.x >> 4;
            int n  = (threadIdx.x & 15) << 2;
            *(float4*)&Bs[kb][n] = *(const float4*)&Bm[(size_t)(k0 + kb) * N + bn + n];
        }
        __syncthreads();
        #pragma unroll
        for (int k = 0; k < 16; k++) {
            float4 a4 = *(const float4*)&As[k][ty * 4];
            float4 b4 = *(const float4*)&Bs[k][tx * 4];
            float a[4] = {a4.x, a4.y, a4.z, a4.w};
            float b[4] = {b4.x, b4.y, b4.z, b4.w};
            #pragma unroll
            for (int i = 0; i < 4; i++)
                #pragma unroll
                for (int j = 0; j < 4; j++)
                    acc[i][j] = fmaf(a[i], b[j], acc[i][j]);
        }
        __syncthreads();
    }

    #pragma unroll
    for (int i = 0; i < 4; i++) {
        int m = bm + ty * 4 + i;
        #pragma unroll
        for (int j = 0; j < 4; j++) {
            int n = bn + tx * 4 + j;
            float vv = acc[i][j];
            if (MODE == 2) {
                C[(size_t)m * N + n] = vv + bias[n];
            } else {
                int b = m >> 12, t = m & 4095;
                int h = n >> 6,  d = n & 63;
                float* dst = (MODE == 0) ? g_qk : g_v;
                dst[(((size_t)(b * 8 + h)) * T + t) * DH + d] = vv;
            }
        }
    }
}

// ---------------- hash (rotations + argmax) + stable counting sort ----------------
// one block per (bh, round); 256 threads
__global__ void hash_sort_kernel(const float* __restrict__ rotations)
{
    int bh = blockIdx.x >> 2;
    int r  = blockIdx.x & 3;

    __shared__ float rot[64][32];
    __shared__ unsigned char bucket[T];
    __shared__ int hist[NB];
    __shared__ int offs[NB];

    int tid = threadIdx.x;
    // rotations layout (DIM_HEAD=64, NH=4, 32)
    for (int x = tid; x < 64 * 32; x += 256) {
        int d = x >> 5, i = x & 31;
        rot[d][i] = rotations[(d * NH + r) * 32 + i];
    }
    if (tid < NB) hist[tid] = 0;
    __syncthreads();

    const float* qkbh = g_qk + (size_t)bh * T * DH;
    for (int t = tid; t < T; t += 256) {
        const float* q = qkbh + (size_t)t * DH;
        float s[32];
        #pragma unroll
        for (int i = 0; i < 32; i++) s[i] = 0.f;
        for (int d4 = 0; d4 < 16; d4++) {
            float4 qv = *(const float4*)&q[d4 * 4];
            #pragma unroll
            for (int i = 0; i < 32; i++) {
                s[i] = fmaf(qv.x, rot[d4 * 4 + 0][i], s[i]);
                s[i] = fmaf(qv.y, rot[d4 * 4 + 1][i], s[i]);
                s[i] = fmaf(qv.z, rot[d4 * 4 + 2][i], s[i]);
                s[i] = fmaf(qv.w, rot[d4 * 4 + 3][i], s[i]);
            }
        }
        // argmax over [s, -s], first occurrence wins (strict >)
        float best = -3.4e38f; int bi = 0;
        #pragma unroll
        for (int i = 0; i < 32; i++) { if (s[i] > best) { best = s[i]; bi = i; } }
        #pragma unroll
        for (int i = 0; i < 32; i++) { float v = -s[i]; if (v > best) { best = v; bi = 32 + i; } }
        bucket[t] = (unsigned char)bi;
        atomicAdd(&hist[bi], 1);
    }
    __syncthreads();

    if (tid == 0) {
        int run = 0;
        for (int b = 0; b < NB; b++) { offs[b] = run; run += hist[b]; }
    }
    __syncthreads();

    // stable scatter: thread b owns bucket b; broadcast scan over t
    if (tid < NB) {
        int b = tid;
        int o = offs[b];
        int* stout = g_st + (bh * NH + r) * T;
        for (int t = 0; t < T; t++) {
            if (bucket[t] == (unsigned char)b) stout[o++] = t;
        }
    }
}

// ---------------- chunked LSH attention ----------------
// one block per (bh, chunk); 256 threads; dynamic smem
#define KPITCH 68
#define DPITCH 132
#define SMEM_ATTN ((128*KPITCH*2 + 64*DPITCH + 128 + 128) * 4)

extern __shared__ float smem[];
__global__ void lsh_attn_kernel()
{
    int bh = blockIdx.x >> 8;
    int c  = blockIdx.x & 255;
    int r  = c >> 6;
    int pc = (c + 255) & 255;   // previous chunk (roll over all 256)

    float* Ks       = smem;                      // 128 x KPITCH (raw keys; rows 0..63 == queries)
    float* Vs       = Ks + 128 * KPITCH;         // 128 x KPITCH
    float* dots     = Vs + 128 * KPITCH;         // 64 x DPITCH
    float* inv_norm = dots + 64 * DPITCH;        // 128
    int*   kpos     = (int*)(inv_norm + 128);    // 128

    int tid = threadIdx.x;
    if (tid < 128) {
        int g = (tid < 64) ? (c * 64 + tid) : (pc * 64 + tid - 64);
        kpos[tid] = g_st[bh * (NH * T) + g];
    }
    __syncthreads();

    // gather K and V rows (2 threads per row, 32 floats each)
    {
        int row  = tid >> 1;
        int half = (tid & 1) << 5;
        int p = kpos[row];
        const float* ksrc = g_qk + ((size_t)bh * T + p) * DH + half;
        const float* vsrc = g_v  + ((size_t)bh * T + p) * DH + half;
        #pragma unroll
        for (int u = 0; u < 8; u++) {
            float4 kv = *(const float4*)&ksrc[u * 4];
            float4 vv = *(const float4*)&vsrc[u * 4];
            int base = row * KPITCH + half + u * 4;
            Ks[base + 0] = kv.x; Ks[base + 1] = kv.y; Ks[base + 2] = kv.z; Ks[base + 3] = kv.w;
            Vs[base + 0] = vv.x; Vs[base + 1] = vv.y; Vs[base + 2] = vv.z; Vs[base + 3] = vv.w;
        }
    }
    __syncthreads();

    if (tid < 128) {
        float ss = 0.f;
        #pragma unroll
        for (int d4 = 0; d4 < 16; d4++) {
            float4 x = *(const float4*)&Ks[tid * KPITCH + d4 * 4];
            ss = fmaf(x.x, x.x, ss); ss = fmaf(x.y, x.y, ss);
            ss = fmaf(x.z, x.z, ss); ss = fmaf(x.w, x.w, ss);
        }
        inv_norm[tid] = 1.0f / fmaxf(sqrtf(ss), 1e-12f);
    }
    __syncthreads();

    int tx = tid & 15, ty = tid >> 4;
    int i0 = ty * 4, j0 = tx * 8;

    // QK^T (q = raw rows 0..63; k = raw rows, normalization folded in at the end)
    {
        float acc[4][8] = {};
        for (int k0 = 0; k0 < 64; k0 += 4) {
            float4 a4[4], b4[8];
            #pragma unroll
            for (int i = 0; i < 4; i++) a4[i] = *(const float4*)&Ks[(i0 + i) * KPITCH + k0];
            #pragma unroll
            for (int j = 0; j < 8; j++) b4[j] = *(const float4*)&Ks[(j0 + j) * KPITCH + k0];
            #pragma unroll
            for (int i = 0; i < 4; i++)
                #pragma unroll
                for (int j = 0; j < 8; j++) {
                    acc[i][j] = fmaf(a4[i].x, b4[j].x, acc[i][j]);
                    acc[i][j] = fmaf(a4[i].y, b4[j].y, acc[i][j]);
                    acc[i][j] = fmaf(a4[i].z, b4[j].z, acc[i][j]);
                    acc[i][j] = fmaf(a4[i].w, b4[j].w, acc[i][j]);
                }
        }
        #pragma unroll
        for (int i = 0; i < 4; i++) {
            int qp = kpos[i0 + i];
            #pragma unroll
            for (int j = 0; j < 8; j++) {
                float v = acc[i][j] * inv_norm[j0 + j] * 0.125f;
                if (kpos[j0 + j] == qp) v = SELF_VAL;
                dots[(i0 + i) * DPITCH + j0 + j] = v;
            }
        }
    }
    __syncthreads();

    // softmax per row + logsumexp (first 64 threads, one row each)
    if (tid < 64) {
        float* row = dots + tid * DPITCH;
        float m = -3.4e38f;
        for (int j = 0; j < 128; j++) m = fmaxf(m, row[j]);
        float s = 0.f;
        for (int j = 0; j < 128; j++) { float e = expf(row[j] - m); row[j] = e; s += e; }
        float invs = 1.0f / s;
        for (int j = 0; j < 128; j++) row[j] *= invs;
        g_lse[((size_t)bh * NH + r) * T + kpos[tid]] = m + logf(s);
    }
    __syncthreads();

    // PV: (64x128) @ (128x64)
    {
        int d0 = tx * 4;
        float acc[4][4] = {};
        for (int k0 = 0; k0 < 128; k0 += 4) {
            float4 a4[4], b4[4];
            #pragma unroll
            for (int i = 0; i < 4; i++) a4[i] = *(const float4*)&dots[(i0 + i) * DPITCH + k0];
            #pragma unroll
            for (int kk = 0; kk < 4; kk++) b4[kk] = *(const float4*)&Vs[(k0 + kk) * KPITCH + d0];
            #pragma unroll
            for (int i = 0; i < 4; i++) {
                float a[4] = {a4[i].x, a4[i].y, a4[i].z, a4[i].w};
                #pragma unroll
                for (int kk = 0; kk < 4; kk++) {
                    acc[i][0] = fmaf(a[kk], b4[kk].x, acc[i][0]);
                    acc[i][1] = fmaf(a[kk], b4[kk].y, acc[i][1]);
                    acc[i][2] = fmaf(a[kk], b4[kk].z, acc[i][2]);
                    acc[i][3] = fmaf(a[kk], b4[kk].w, acc[i][3]);
                }
            }
        }
        #pragma unroll
        for (int i = 0; i < 4; i++) {
            size_t base = (((size_t)bh * NH + r) * T + kpos[i0 + i]) * DH + d0;
            #pragma unroll
            for (int j = 0; j < 4; j++) g_o[base + j] = acc[i][j];
        }
    }
}

// ---------------- combine hash rounds ----------------
__global__ void combine_kernel()
{
    int idx = blockIdx.x * 256 + threadIdx.x;     // < 32*4096*64
    int d   = idx & 63;
    int pos = (idx >> 6) & 4095;
    int bh  = idx >> 18;

    float l[4];
    #pragma unroll
    for (int r = 0; r < 4; r++) l[r] = g_lse[((size_t)bh * 4 + r) * T + pos];
    float m = fmaxf(fmaxf(l[0], l[1]), fmaxf(l[2], l[3]));
    float w[4], ws = 0.f;
    #pragma unroll
    for (int r = 0; r < 4; r++) { w[r] = expf(l[r] - m); ws += w[r]; }
    float o = 0.f;
    #pragma unroll
    for (int r = 0; r < 4; r++)
        o += w[r] * g_o[(((size_t)bh * 4 + r) * T + pos) * DH + d];
    o /= ws;

    int b = bh >> 3, h = bh & 7;
    g_ctx[((size_t)b * T + pos) * DM + h * 64 + d] = o;
}

// ---------------- launch ----------------
extern "C" void kernel_launch(void* const* d_in, const int* in_sizes, int n_in,
                              void* d_out, int out_size)
{
    (void)in_sizes; (void)n_in; (void)out_size;
    const float* queries   = (const float*)d_in[0];
    const float* W_qk      = (const float*)d_in[3];
    const float* W_v       = (const float*)d_in[4];
    const float* W_out     = (const float*)d_in[5];
    const float* b_out     = (const float*)d_in[6];
    const float* rotations = (const float*)d_in[7];
    float* out = (float*)d_out;

    dim3 gg(512 / 64, 16384 / 64);   // (N tiles, M tiles)

    gemm_kernel<0><<<gg, 256>>>(queries, W_qk, nullptr, nullptr);
    gemm_kernel<1><<<gg, 256>>>(queries, W_v,  nullptr, nullptr);

    hash_sort_kernel<<<BHN * NH, 256>>>(rotations);

    cudaFuncSetAttribute(lsh_attn_kernel,
                         cudaFuncAttributeMaxDynamicSharedMemorySize, SMEM_ATTN);
    lsh_attn_kernel<<<BHN * 256, 256, SMEM_ATTN>>>();

    combine_kernel<<<(BHN * T * DH) / 256, 256>>>();

    gemm_kernel<2><<<gg, 256>>>(nullptr, W_out, b_out, out);
}

// round 3
// speedup vs baseline: 1.1562x; 1.1562x over previous
#include <cuda_runtime.h>
#include <math.h>

// Problem constants
#define T      4096
#define DH     64
#define NH     4        // n_hashes
#define NB     64       // buckets per hash
#define DM     512
#define BHN    32       // B*H
#define SELF_VAL (-5e4f)

// ---------------- scratch (device globals; no allocation allowed) ----------------
__device__ float g_qk [(size_t)BHN * T * DH];        // merged qk  (bh, t, dh)
__device__ float g_v  [(size_t)BHN * T * DH];        // merged v
__device__ int   g_st [BHN * NH * T];                // sorted original positions
__device__ float g_o  [(size_t)BHN * NH * T * DH];   // per-round outputs
__device__ float g_lse[BHN * NH * T];                // per-round logsumexp
__device__ float g_ctx[(size_t)4 * T * DM];          // combined context (B,T,DM)

// ---------------- GEMM: C[16384,512] = A[16384,512] @ B[512,512] ----------------
// 128x64 tile, 8x4 per thread, double-buffered smem, 1 sync/stage.
// MODE 0: A=param, write merged -> g_qk ; MODE 1: -> g_v ; MODE 2: A=g_ctx, C+bias
template <int MODE>
__global__ __launch_bounds__(256)
void gemm_kernel(const float* __restrict__ A,
                 const float* __restrict__ Bm,
                 const float* __restrict__ bias,
                 float* __restrict__ C)
{
    const int N = 512, K = 512;
    __shared__ float As[2][16][132];   // [k][m]
    __shared__ float Bs[2][16][68];    // [k][n]
    const float* Ap = (MODE == 2) ? g_ctx : A;

    int tid = threadIdx.x;
    int tx = tid & 15, ty = tid >> 4;
    int bm = blockIdx.y * 128, bn = blockIdx.x * 64;

    // load mapping
    int f0 = tid * 2, f1 = tid * 2 + 1;
    int a_row0 = f0 >> 2, a_k0 = (f0 & 3) << 2;
    int a_row1 = f1 >> 2, a_k1 = (f1 & 3) << 2;
    int b_k = tid >> 4, b_n = (tid & 15) << 2;

    float4 ar0, ar1, br;
    float acc[8][4] = {};

#define LDG_TILE(k0)                                                              \
    {   ar0 = *(const float4*)&Ap[(size_t)(bm + a_row0) * K + (k0) + a_k0];       \
        ar1 = *(const float4*)&Ap[(size_t)(bm + a_row1) * K + (k0) + a_k1];       \
        br  = *(const float4*)&Bm[(size_t)((k0) + b_k) * N + bn + b_n]; }
#define STS_TILE(buf)                                                             \
    {   As[buf][a_k0 + 0][a_row0] = ar0.x; As[buf][a_k0 + 1][a_row0] = ar0.y;     \
        As[buf][a_k0 + 2][a_row0] = ar0.z; As[buf][a_k0 + 3][a_row0] = ar0.w;     \
        As[buf][a_k1 + 0][a_row1] = ar1.x; As[buf][a_k1 + 1][a_row1] = ar1.y;     \
        As[buf][a_k1 + 2][a_row1] = ar1.z; As[buf][a_k1 + 3][a_row1] = ar1.w;     \
        *(float4*)&Bs[buf][b_k][b_n] = br; }

    LDG_TILE(0); STS_TILE(0); __syncthreads();

    const int NST = K / 16;   // 32
    for (int s = 0; s < NST; s++) {
        if (s + 1 < NST) LDG_TILE((s + 1) * 16);
        int buf = s & 1;
        #pragma unroll
        for (int k = 0; k < 16; k++) {
            float4 a0 = *(const float4*)&As[buf][k][ty * 8];
            float4 a1 = *(const float4*)&As[buf][k][ty * 8 + 4];
            float4 b4 = *(const float4*)&Bs[buf][k][tx * 4];
            float a[8] = {a0.x, a0.y, a0.z, a0.w, a1.x, a1.y, a1.z, a1.w};
            float b[4] = {b4.x, b4.y, b4.z, b4.w};
            #pragma unroll
            for (int i = 0; i < 8; i++)
                #pragma unroll
                for (int j = 0; j < 4; j++)
                    acc[i][j] = fmaf(a[i], b[j], acc[i][j]);
        }
        if (s + 1 < NST) STS_TILE((s + 1) & 1);
        __syncthreads();
    }

    #pragma unroll
    for (int i = 0; i < 8; i++) {
        int m = bm + ty * 8 + i;
        #pragma unroll
        for (int j = 0; j < 4; j++) {
            int n = bn + tx * 4 + j;
            float vv = acc[i][j];
            if (MODE == 2) {
                C[(size_t)m * N + n] = vv + bias[n];
            } else {
                int b = m >> 12, t = m & 4095;
                int h = n >> 6,  d = n & 63;
                float* dst = (MODE == 0) ? g_qk : g_v;
                dst[(((size_t)(b * 8 + h)) * T + t) * DH + d] = vv;
            }
        }
    }
#undef LDG_TILE
#undef STS_TILE
}

// ---------------- hash (rotations + argmax) + stable counting sort ----------------
// one block per (bh, round); 256 threads; 4-way parallel stable scatter
__global__ void hash_sort_kernel(const float* __restrict__ rotations)
{
    int bh = blockIdx.x >> 2;
    int r  = blockIdx.x & 3;

    __shared__ float rot[64][32];
    __shared__ unsigned char bucket[T];
    __shared__ int hist4[4][NB];      // [quarter][bucket]
    __shared__ int offs[NB];
    __shared__ int tot[NB];

    int tid = threadIdx.x;
    for (int x = tid; x < 64 * 32; x += 256) {
        int d = x >> 5, i = x & 31;
        rot[d][i] = rotations[(d * NH + r) * 32 + i];
    }
    ((int*)hist4)[tid] = 0;
    __syncthreads();

    const float* qkbh = g_qk + (size_t)bh * T * DH;
    for (int t = tid; t < T; t += 256) {
        const float* q = qkbh + (size_t)t * DH;
        float s[32];
        #pragma unroll
        for (int i = 0; i < 32; i++) s[i] = 0.f;
        for (int d4 = 0; d4 < 16; d4++) {
            float4 qv = *(const float4*)&q[d4 * 4];
            #pragma unroll
            for (int i = 0; i < 32; i++) {
                s[i] = fmaf(qv.x, rot[d4 * 4 + 0][i], s[i]);
                s[i] = fmaf(qv.y, rot[d4 * 4 + 1][i], s[i]);
                s[i] = fmaf(qv.z, rot[d4 * 4 + 2][i], s[i]);
                s[i] = fmaf(qv.w, rot[d4 * 4 + 3][i], s[i]);
            }
        }
        float best = -3.4e38f; int bi = 0;
        #pragma unroll
        for (int i = 0; i < 32; i++) { if (s[i] > best) { best = s[i]; bi = i; } }
        #pragma unroll
        for (int i = 0; i < 32; i++) { float v = -s[i]; if (v > best) { best = v; bi = 32 + i; } }
        bucket[t] = (unsigned char)bi;
        atomicAdd(&hist4[t >> 10][bi], 1);
    }
    __syncthreads();

    if (tid < NB)
        tot[tid] = hist4[0][tid] + hist4[1][tid] + hist4[2][tid] + hist4[3][tid];
    __syncthreads();
    if (tid == 0) {
        int run = 0;
        for (int b = 0; b < NB; b++) { offs[b] = run; run += tot[b]; }
    }
    __syncthreads();

    // thread -> (bucket b, quarter q): stable scatter of its 1024-range
    {
        int b = tid & 63, q = tid >> 6;
        int o = offs[b];
        #pragma unroll
        for (int qq = 0; qq < 3; qq++) if (qq < q) o += hist4[qq][b];
        int* stout = g_st + (bh * NH + r) * T;
        int t0 = q << 10;
        for (int t = t0; t < t0 + 1024; t++) {
            if (bucket[t] == (unsigned char)b) stout[o++] = t;
        }
    }
}

// ---------------- chunked LSH attention ----------------
// one block per (bh, chunk); 256 threads; dots overlays Ks after QK.
// KP MUST be a multiple of 4: float4 LDS from &Ks[row*KP + 4k] requires 16B alignment.
#define KP 68
#define DP 132
// floats: Ks 128*KP + Vs 128*KP + inv_norm 128 + red 256 + red2 256 + invs 64 ; ints: kpos 128
#define SMEM_ATTN ((128*KP*2 + 128 + 256 + 256 + 64 + 128) * 4)

extern __shared__ float smem[];
__global__ __launch_bounds__(256, 3)
void lsh_attn_kernel()
{
    int bh = blockIdx.x >> 8;
    int c  = blockIdx.x & 255;
    int r  = c >> 6;
    int pc = (c + 255) & 255;

    float* Ks       = smem;                      // 128 x KP  (rows 0..63 are also queries)
    float* Vs       = Ks + 128 * KP;             // 128 x KP
    float* inv_norm = Vs + 128 * KP;             // 128
    float* red      = inv_norm + 128;            // 64 x 4 (max partials)
    float* red2     = red + 256;                 // 64 x 4 (sum partials)
    float* invs     = red2 + 256;                // 64
    int*   kpos     = (int*)(invs + 64);         // 128
    float* dots     = Ks;                        // overlay: 64 x DP (=8448 floats <= 128*KP)

    int tid = threadIdx.x;
    if (tid < 128) {
        int g = (tid < 64) ? (c * 64 + tid) : (pc * 64 + tid - 64);
        kpos[tid] = g_st[bh * (NH * T) + g];
    }
    __syncthreads();

    // gather K and V rows (2 threads per row, 32 floats each)
    {
        int row  = tid >> 1;
        int half = (tid & 1) << 5;
        int p = kpos[row];
        const float* ksrc = g_qk + ((size_t)bh * T + p) * DH + half;
        const float* vsrc = g_v  + ((size_t)bh * T + p) * DH + half;
        #pragma unroll
        for (int u = 0; u < 8; u++) {
            float4 kv = *(const float4*)&ksrc[u * 4];
            float4 vv = *(const float4*)&vsrc[u * 4];
            int base = row * KP + half + u * 4;
            Ks[base + 0] = kv.x; Ks[base + 1] = kv.y; Ks[base + 2] = kv.z; Ks[base + 3] = kv.w;
            Vs[base + 0] = vv.x; Vs[base + 1] = vv.y; Vs[base + 2] = vv.z; Vs[base + 3] = vv.w;
        }
    }
    __syncthreads();

    if (tid < 128) {
        float ss = 0.f;
        #pragma unroll
        for (int d4 = 0; d4 < 16; d4++) {
            float4 x = *(const float4*)&Ks[tid * KP + d4 * 4];
            ss = fmaf(x.x, x.x, ss); ss = fmaf(x.y, x.y, ss);
            ss = fmaf(x.z, x.z, ss); ss = fmaf(x.w, x.w, ss);
        }
        inv_norm[tid] = 1.0f / fmaxf(sqrtf(ss), 1e-12f);
    }
    __syncthreads();

    int tx = tid & 15, ty = tid >> 4;
    int i0 = ty * 4, j0 = tx * 8;

    // QK^T into registers (q = raw rows 0..63; key-normalization folded at the end)
    float qkacc[4][8] = {};
    for (int k0 = 0; k0 < 64; k0 += 4) {
        float4 a4[4], b4[8];
        #pragma unroll
        for (int i = 0; i < 4; i++) a4[i] = *(const float4*)&Ks[(i0 + i) * KP + k0];
        #pragma unroll
        for (int j = 0; j < 8; j++) b4[j] = *(const float4*)&Ks[(j0 + j) * KP + k0];
        #pragma unroll
        for (int i = 0; i < 4; i++)
            #pragma unroll
            for (int j = 0; j < 8; j++) {
                qkacc[i][j] = fmaf(a4[i].x, b4[j].x, qkacc[i][j]);
                qkacc[i][j] = fmaf(a4[i].y, b4[j].y, qkacc[i][j]);
                qkacc[i][j] = fmaf(a4[i].z, b4[j].z, qkacc[i][j]);
                qkacc[i][j] = fmaf(a4[i].w, b4[j].w, qkacc[i][j]);
            }
    }
    // scale + mask in registers
    float inj[8];
    int   pj[8];
    #pragma unroll
    for (int j = 0; j < 8; j++) { inj[j] = inv_norm[j0 + j]; pj[j] = kpos[j0 + j]; }
    #pragma unroll
    for (int i = 0; i < 4; i++) {
        int qp = kpos[i0 + i];
        #pragma unroll
        for (int j = 0; j < 8; j++) {
            float v = qkacc[i][j] * inj[j] * 0.125f;
            qkacc[i][j] = (pj[j] == qp) ? SELF_VAL : v;
        }
    }
    __syncthreads();   // all reads of Ks done -> safe to overlay

    #pragma unroll
    for (int i = 0; i < 4; i++)
        #pragma unroll
        for (int j = 0; j < 8; j++)
            dots[(i0 + i) * DP + j0 + j] = qkacc[i][j];
    __syncthreads();

    // ---- parallel softmax: thread -> (row = tid>>2, seg = tid&3), strided columns
    {
        int row = tid >> 2, seg = tid & 3;
        float* drow = dots + row * DP;
        float mp = -3.4e38f;
        #pragma unroll
        for (int k = 0; k < 32; k++) mp = fmaxf(mp, drow[seg + 4 * k]);
        red[row * 4 + seg] = mp;
        __syncthreads();

        float m = fmaxf(fmaxf(red[row * 4 + 0], red[row * 4 + 1]),
                        fmaxf(red[row * 4 + 2], red[row * 4 + 3]));
        float sp = 0.f;
        #pragma unroll
        for (int k = 0; k < 32; k++) {
            float e = __expf(drow[seg + 4 * k] - m);
            drow[seg + 4 * k] = e;
            sp += e;
        }
        red2[row * 4 + seg] = sp;
        __syncthreads();

        if (tid < 64) {
            float mm = fmaxf(fmaxf(red[tid * 4 + 0], red[tid * 4 + 1]),
                             fmaxf(red[tid * 4 + 2], red[tid * 4 + 3]));
            float s = red2[tid * 4 + 0] + red2[tid * 4 + 1] + red2[tid * 4 + 2] + red2[tid * 4 + 3];
            invs[tid] = 1.0f / s;
            g_lse[((size_t)bh * NH + r) * T + kpos[tid]] = mm + logf(s);
        }
        __syncthreads();
    }

    // ---- PV: (64x128) @ (128x64), 1/sum folded into epilogue
    {
        int d0 = tx * 4;
        float acc[4][4] = {};
        for (int k0 = 0; k0 < 128; k0 += 4) {
            float4 a4[4], b4[4];
            #pragma unroll
            for (int i = 0; i < 4; i++) a4[i] = *(const float4*)&dots[(i0 + i) * DP + k0];
            #pragma unroll
            for (int kk = 0; kk < 4; kk++) b4[kk] = *(const float4*)&Vs[(k0 + kk) * KP + d0];
            #pragma unroll
            for (int i = 0; i < 4; i++) {
                float a[4] = {a4[i].x, a4[i].y, a4[i].z, a4[i].w};
                #pragma unroll
                for (int kk = 0; kk < 4; kk++) {
                    acc[i][0] = fmaf(a[kk], b4[kk].x, acc[i][0]);
                    acc[i][1] = fmaf(a[kk], b4[kk].y, acc[i][1]);
                    acc[i][2] = fmaf(a[kk], b4[kk].z, acc[i][2]);
                    acc[i][3] = fmaf(a[kk], b4[kk].w, acc[i][3]);
                }
            }
        }
        #pragma unroll
        for (int i = 0; i < 4; i++) {
            float sc = invs[i0 + i];
            size_t base = (((size_t)bh * NH + r) * T + kpos[i0 + i]) * DH + d0;
            #pragma unroll
            for (int j = 0; j < 4; j++) g_o[base + j] = acc[i][j] * sc;
        }
    }
}

// ---------------- combine hash rounds ----------------
__global__ void combine_kernel()
{
    int idx = blockIdx.x * 256 + threadIdx.x;
    int d   = idx & 63;
    int pos = (idx >> 6) & 4095;
    int bh  = idx >> 18;

    float l[4];
    #pragma unroll
    for (int r = 0; r < 4; r++) l[r] = g_lse[((size_t)bh * 4 + r) * T + pos];
    float m = fmaxf(fmaxf(l[0], l[1]), fmaxf(l[2], l[3]));
    float w[4], ws = 0.f;
    #pragma unroll
    for (int r = 0; r < 4; r++) { w[r] = __expf(l[r] - m); ws += w[r]; }
    float o = 0.f;
    #pragma unroll
    for (int r = 0; r < 4; r++)
        o += w[r] * g_o[(((size_t)bh * 4 + r) * T + pos) * DH + d];
    o /= ws;

    int b = bh >> 3, h = bh & 7;
    g_ctx[((size_t)b * T + pos) * DM + h * 64 + d] = o;
}

// ---------------- launch ----------------
extern "C" void kernel_launch(void* const* d_in, const int* in_sizes, int n_in,
                              void* d_out, int out_size)
{
    (void)in_sizes; (void)n_in; (void)out_size;
    const float* queries   = (const float*)d_in[0];
    const float* W_qk      = (const float*)d_in[3];
    const float* W_v       = (const float*)d_in[4];
    const float* W_out     = (const float*)d_in[5];
    const float* b_out     = (const float*)d_in[6];
    const float* rotations = (const float*)d_in[7];
    float* out = (float*)d_out;

    dim3 gg(512 / 64, 16384 / 128);

    gemm_kernel<0><<<gg, 256>>>(queries, W_qk, nullptr, nullptr);
    gemm_kernel<1><<<gg, 256>>>(queries, W_v,  nullptr, nullptr);

    hash_sort_kernel<<<BHN * NH, 256>>>(rotations);

    cudaFuncSetAttribute(lsh_attn_kernel,
                         cudaFuncAttributeMaxDynamicSharedMemorySize, SMEM_ATTN);
    lsh_attn_kernel<<<BHN * 256, 256, SMEM_ATTN>>>();

    combine_kernel<<<(BHN * T * DH) / 256, 256>>>();

    gemm_kernel<2><<<gg, 256>>>(nullptr, W_out, b_out, out);
}

// round 4
// speedup vs baseline: 1.8530x; 1.6027x over previous
#include <cuda_runtime.h>
#include <math.h>

// Problem constants
#define T      4096
#define DH     64
#define NH     4        // n_hashes
#define NB     64       // buckets per hash
#define DM     512
#define BHN    32       // B*H
#define SELF_VAL (-5e4f)

// ---------------- scratch (device globals; no allocation allowed) ----------------
__device__ float g_qk [(size_t)BHN * T * DH];        // merged qk  (bh, t, dh)
__device__ float g_v  [(size_t)BHN * T * DH];        // merged v
__device__ int   g_st [BHN * NH * T];                // sorted original positions
__device__ float g_o  [(size_t)BHN * NH * T * DH];   // per-round outputs
__device__ float g_lse[BHN * NH * T];                // per-round logsumexp
__device__ float g_ctx[(size_t)4 * T * DM];          // combined context (B,T,DM)

// ---------------- GEMM: C[16384,512] = A[16384,512] @ B[512,512] ----------------
// 128x64 tile, 8x4 per thread, double-buffered smem, 1 sync/stage. (fp32 FMA-bound)
template <int MODE>
__global__ __launch_bounds__(256)
void gemm_kernel(const float* __restrict__ A,
                 const float* __restrict__ Bm,
                 const float* __restrict__ bias,
                 float* __restrict__ C)
{
    const int N = 512, K = 512;
    __shared__ float As[2][16][132];   // [k][m]
    __shared__ float Bs[2][16][68];    // [k][n]
    const float* Ap = (MODE == 2) ? g_ctx : A;

    int tid = threadIdx.x;
    int tx = tid & 15, ty = tid >> 4;
    int bm = blockIdx.y * 128, bn = blockIdx.x * 64;

    int f0 = tid * 2, f1 = tid * 2 + 1;
    int a_row0 = f0 >> 2, a_k0 = (f0 & 3) << 2;
    int a_row1 = f1 >> 2, a_k1 = (f1 & 3) << 2;
    int b_k = tid >> 4, b_n = (tid & 15) << 2;

    float4 ar0, ar1, br;
    float acc[8][4] = {};

#define LDG_TILE(k0)                                                              \
    {   ar0 = *(const float4*)&Ap[(size_t)(bm + a_row0) * K + (k0) + a_k0];       \
        ar1 = *(const float4*)&Ap[(size_t)(bm + a_row1) * K + (k0) + a_k1];       \
        br  = *(const float4*)&Bm[(size_t)((k0) + b_k) * N + bn + b_n]; }
#define STS_TILE(buf)                                                             \
    {   As[buf][a_k0 + 0][a_row0] = ar0.x; As[buf][a_k0 + 1][a_row0] = ar0.y;     \
        As[buf][a_k0 + 2][a_row0] = ar0.z; As[buf][a_k0 + 3][a_row0] = ar0.w;     \
        As[buf][a_k1 + 0][a_row1] = ar1.x; As[buf][a_k1 + 1][a_row1] = ar1.y;     \
        As[buf][a_k1 + 2][a_row1] = ar1.z; As[buf][a_k1 + 3][a_row1] = ar1.w;     \
        *(float4*)&Bs[buf][b_k][b_n] = br; }

    LDG_TILE(0); STS_TILE(0); __syncthreads();

    const int NST = K / 16;   // 32
    for (int s = 0; s < NST; s++) {
        if (s + 1 < NST) LDG_TILE((s + 1) * 16);
        int buf = s & 1;
        #pragma unroll
        for (int k = 0; k < 16; k++) {
            float4 a0 = *(const float4*)&As[buf][k][ty * 8];
            float4 a1 = *(const float4*)&As[buf][k][ty * 8 + 4];
            float4 b4 = *(const float4*)&Bs[buf][k][tx * 4];
            float a[8] = {a0.x, a0.y, a0.z, a0.w, a1.x, a1.y, a1.z, a1.w};
            float b[4] = {b4.x, b4.y, b4.z, b4.w};
            #pragma unroll
            for (int i = 0; i < 8; i++)
                #pragma unroll
                for (int j = 0; j < 4; j++)
                    acc[i][j] = fmaf(a[i], b[j], acc[i][j]);
        }
        if (s + 1 < NST) STS_TILE((s + 1) & 1);
        __syncthreads();
    }

    #pragma unroll
    for (int i = 0; i < 8; i++) {
        int m = bm + ty * 8 + i;
        #pragma unroll
        for (int j = 0; j < 4; j++) {
            int n = bn + tx * 4 + j;
            float vv = acc[i][j];
            if (MODE == 2) {
                C[(size_t)m * N + n] = vv + bias[n];
            } else {
                int b = m >> 12, t = m & 4095;
                int h = n >> 6,  d = n & 63;
                float* dst = (MODE == 0) ? g_qk : g_v;
                dst[(((size_t)(b * 8 + h)) * T + t) * DH + d] = vv;
            }
        }
    }
#undef LDG_TILE
#undef STS_TILE
}

// ---------------- hash (rotations + argmax) + stable counting sort ----------------
__global__ void hash_sort_kernel(const float* __restrict__ rotations)
{
    int bh = blockIdx.x >> 2;
    int r  = blockIdx.x & 3;

    __shared__ float rot[64][32];
    __shared__ unsigned char bucket[T];
    __shared__ int hist4[4][NB];
    __shared__ int offs[NB];
    __shared__ int tot[NB];

    int tid = threadIdx.x;
    for (int x = tid; x < 64 * 32; x += 256) {
        int d = x >> 5, i = x & 31;
        rot[d][i] = rotations[(d * NH + r) * 32 + i];
    }
    ((int*)hist4)[tid] = 0;
    __syncthreads();

    const float* qkbh = g_qk + (size_t)bh * T * DH;
    for (int t = tid; t < T; t += 256) {
        const float* q = qkbh + (size_t)t * DH;
        float s[32];
        #pragma unroll
        for (int i = 0; i < 32; i++) s[i] = 0.f;
        for (int d4 = 0; d4 < 16; d4++) {
            float4 qv = *(const float4*)&q[d4 * 4];
            #pragma unroll
            for (int i = 0; i < 32; i++) {
                s[i] = fmaf(qv.x, rot[d4 * 4 + 0][i], s[i]);
                s[i] = fmaf(qv.y, rot[d4 * 4 + 1][i], s[i]);
                s[i] = fmaf(qv.z, rot[d4 * 4 + 2][i], s[i]);
                s[i] = fmaf(qv.w, rot[d4 * 4 + 3][i], s[i]);
            }
        }
        float best = -3.4e38f; int bi = 0;
        #pragma unroll
        for (int i = 0; i < 32; i++) { if (s[i] > best) { best = s[i]; bi = i; } }
        #pragma unroll
        for (int i = 0; i < 32; i++) { float v = -s[i]; if (v > best) { best = v; bi = 32 + i; } }
        bucket[t] = (unsigned char)bi;
        atomicAdd(&hist4[t >> 10][bi], 1);
    }
    __syncthreads();

    if (tid < NB)
        tot[tid] = hist4[0][tid] + hist4[1][tid] + hist4[2][tid] + hist4[3][tid];
    __syncthreads();
    if (tid == 0) {
        int run = 0;
        for (int b = 0; b < NB; b++) { offs[b] = run; run += tot[b]; }
    }
    __syncthreads();

    {
        int b = tid & 63, q = tid >> 6;
        int o = offs[b];
        #pragma unroll
        for (int qq = 0; qq < 3; qq++) if (qq < q) o += hist4[qq][b];
        int* stout = g_st + (bh * NH + r) * T;
        int t0 = q << 10;
        for (int t = t0; t < t0 + 1024; t++) {
            if (bucket[t] == (unsigned char)b) stout[o++] = t;
        }
    }
}

// ---------------- chunked LSH attention (conflict-free layout) ----------------
// Kt: transposed K [dh=64][128 rows], pitch 136 floats (544B: 16B-aligned, good bank spread)
// Vs: row-major   [128 rows][64],    pitch  68 floats
// dots overlays Kt after QK.
#define KTP 136
#define VP  68
#define DP  132
// floats: Kt 64*KTP + Vs 128*VP + inv_norm 128 + invs 64 ; ints kpos 128
#define SMEM_ATTN ((64*KTP + 128*VP + 128 + 64 + 128) * 4)

extern __shared__ float smem[];
__global__ __launch_bounds__(256, 3)
void lsh_attn_kernel()
{
    int bh = blockIdx.x >> 8;
    int c  = blockIdx.x & 255;
    int r  = c >> 6;
    int pc = (c + 255) & 255;

    float* Kt       = smem;                      // 64 x KTP   (Kt[k][row])
    float* Vs       = Kt + 64 * KTP;             // 128 x VP
    float* inv_norm = Vs + 128 * VP;             // 128
    float* invs     = inv_norm + 128;            // 64
    int*   kpos     = (int*)(invs + 64);         // 128
    float* dots     = Kt;                        // overlay: 64 x DP (8448 <= 8704)

    int tid = threadIdx.x;
    if (tid < 128) {
        int g = (tid < 64) ? (c * 64 + tid) : (pc * 64 + tid - 64);
        kpos[tid] = g_st[bh * (NH * T) + g];
    }
    __syncthreads();

    // gather: 2 threads per row, 32 floats each; K -> transposed smem; norm via shfl pair
    {
        int row  = tid >> 1;
        int half = (tid & 1) << 5;
        int p = kpos[row];
        const float* ksrc = g_qk + ((size_t)bh * T + p) * DH + half;
        const float* vsrc = g_v  + ((size_t)bh * T + p) * DH + half;
        float ss = 0.f;
        #pragma unroll
        for (int u = 0; u < 8; u++) {
            float4 kv = *(const float4*)&ksrc[u * 4];
            float4 vv = *(const float4*)&vsrc[u * 4];
            int k = half + u * 4;
            Kt[(k + 0) * KTP + row] = kv.x;
            Kt[(k + 1) * KTP + row] = kv.y;
            Kt[(k + 2) * KTP + row] = kv.z;
            Kt[(k + 3) * KTP + row] = kv.w;
            *(float4*)&Vs[row * VP + k] = vv;
            ss = fmaf(kv.x, kv.x, ss); ss = fmaf(kv.y, kv.y, ss);
            ss = fmaf(kv.z, kv.z, ss); ss = fmaf(kv.w, kv.w, ss);
        }
        ss += __shfl_xor_sync(0xffffffffu, ss, 1);
        if ((tid & 1) == 0)
            inv_norm[row] = 1.0f / fmaxf(sqrtf(ss), 1e-12f);
    }
    __syncthreads();

    int tx = tid & 15, ty = tid >> 4;
    int i0 = ty * 4;
    // j columns: {2tx+32g, 2tx+32g+1 : g=0..3}  -> conflict-free float2 b-loads

    // ---- QK^T into registers
    float qkacc[4][8] = {};   // [i][2g+h]
    #pragma unroll 4
    for (int k = 0; k < 64; k++) {
        const float* krow = Kt + k * KTP;
        float4 a = *(const float4*)&krow[i0];
        float2 b0 = *(const float2*)&krow[2 * tx];
        float2 b1 = *(const float2*)&krow[2 * tx + 32];
        float2 b2 = *(const float2*)&krow[2 * tx + 64];
        float2 b3 = *(const float2*)&krow[2 * tx + 96];
        float av[4] = {a.x, a.y, a.z, a.w};
        float bv[8] = {b0.x, b0.y, b1.x, b1.y, b2.x, b2.y, b3.x, b3.y};
        #pragma unroll
        for (int i = 0; i < 4; i++)
            #pragma unroll
            for (int j = 0; j < 8; j++)
                qkacc[i][j] = fmaf(av[i], bv[j], qkacc[i][j]);
    }

    // scale + self-mask in registers
    float inj[8];
    int   pj[8];
    #pragma unroll
    for (int g = 0; g < 4; g++) {
        int j = 2 * tx + 32 * g;
        inj[2 * g]     = inv_norm[j];     pj[2 * g]     = kpos[j];
        inj[2 * g + 1] = inv_norm[j + 1]; pj[2 * g + 1] = kpos[j + 1];
    }
    #pragma unroll
    for (int i = 0; i < 4; i++) {
        int qp = kpos[i0 + i];
        #pragma unroll
        for (int j = 0; j < 8; j++) {
            float v = qkacc[i][j] * inj[j] * 0.125f;
            qkacc[i][j] = (pj[j] == qp) ? SELF_VAL : v;
        }
    }
    __syncthreads();   // all Kt reads done -> overlay with dots

    #pragma unroll
    for (int i = 0; i < 4; i++) {
        float* drow = dots + (i0 + i) * DP;
        #pragma unroll
        for (int g = 0; g < 4; g++)
            *(float2*)&drow[2 * tx + 32 * g] =
                make_float2(qkacc[i][2 * g], qkacc[i][2 * g + 1]);
    }
    __syncthreads();

    // ---- softmax: thread -> (row = tid>>2, seg = tid&3); shuffle reduce within quad
    {
        int row = tid >> 2, seg = tid & 3;
        float* drow = dots + row * DP;
        float mp = -3.4e38f;
        #pragma unroll
        for (int k = 0; k < 32; k++) mp = fmaxf(mp, drow[seg + 4 * k]);
        mp = fmaxf(mp, __shfl_xor_sync(0xffffffffu, mp, 1));
        mp = fmaxf(mp, __shfl_xor_sync(0xffffffffu, mp, 2));
        float sp = 0.f;
        #pragma unroll
        for (int k = 0; k < 32; k++) {
            float e = __expf(drow[seg + 4 * k] - mp);
            drow[seg + 4 * k] = e;
            sp += e;
        }
        sp += __shfl_xor_sync(0xffffffffu, sp, 1);
        sp += __shfl_xor_sync(0xffffffffu, sp, 2);
        if (seg == 0) {
            invs[row] = 1.0f / sp;
            g_lse[((size_t)bh * NH + r) * T + kpos[row]] = mp + logf(sp);
        }
    }
    __syncthreads();

    // ---- PV: (64x128) @ (128x64); d cols = {2tx, 2tx+1, 2tx+32, 2tx+33}
    {
        float acc[4][4] = {};
        #pragma unroll 2
        for (int k = 0; k < 128; k += 2) {
            float2 ap[4];
            #pragma unroll
            for (int i = 0; i < 4; i++)
                ap[i] = *(const float2*)&dots[(i0 + i) * DP + k];
            float2 v00 = *(const float2*)&Vs[k * VP + 2 * tx];
            float2 v01 = *(const float2*)&Vs[k * VP + 2 * tx + 32];
            float2 v10 = *(const float2*)&Vs[(k + 1) * VP + 2 * tx];
            float2 v11 = *(const float2*)&Vs[(k + 1) * VP + 2 * tx + 32];
            #pragma unroll
            for (int i = 0; i < 4; i++) {
                acc[i][0] = fmaf(ap[i].x, v00.x, acc[i][0]);
                acc[i][1] = fmaf(ap[i].x, v00.y, acc[i][1]);
                acc[i][2] = fmaf(ap[i].x, v01.x, acc[i][2]);
                acc[i][3] = fmaf(ap[i].x, v01.y, acc[i][3]);
                acc[i][0] = fmaf(ap[i].y, v10.x, acc[i][0]);
                acc[i][1] = fmaf(ap[i].y, v10.y, acc[i][1]);
                acc[i][2] = fmaf(ap[i].y, v11.x, acc[i][2]);
                acc[i][3] = fmaf(ap[i].y, v11.y, acc[i][3]);
            }
        }
        #pragma unroll
        for (int i = 0; i < 4; i++) {
            float sc = invs[i0 + i];
            size_t base = (((size_t)bh * NH + r) * T + kpos[i0 + i]) * DH;
            *(float2*)&g_o[base + 2 * tx]      = make_float2(acc[i][0] * sc, acc[i][1] * sc);
            *(float2*)&g_o[base + 2 * tx + 32] = make_float2(acc[i][2] * sc, acc[i][3] * sc);
        }
    }
}

// ---------------- combine hash rounds ----------------
__global__ void combine_kernel()
{
    int idx = blockIdx.x * 256 + threadIdx.x;
    int d   = idx & 63;
    int pos = (idx >> 6) & 4095;
    int bh  = idx >> 18;

    float l[4];
    #pragma unroll
    for (int r = 0; r < 4; r++) l[r] = g_lse[((size_t)bh * 4 + r) * T + pos];
    float m = fmaxf(fmaxf(l[0], l[1]), fmaxf(l[2], l[3]));
    float w[4], ws = 0.f;
    #pragma unroll
    for (int r = 0; r < 4; r++) { w[r] = __expf(l[r] - m); ws += w[r]; }
    float o = 0.f;
    #pragma unroll
    for (int r = 0; r < 4; r++)
        o += w[r] * g_o[(((size_t)bh * 4 + r) * T + pos) * DH + d];
    o /= ws;

    int b = bh >> 3, h = bh & 7;
    g_ctx[((size_t)b * T + pos) * DM + h * 64 + d] = o;
}

// ---------------- launch ----------------
extern "C" void kernel_launch(void* const* d_in, const int* in_sizes, int n_in,
                              void* d_out, int out_size)
{
    (void)in_sizes; (void)n_in; (void)out_size;
    const float* queries   = (const float*)d_in[0];
    const float* W_qk      = (const float*)d_in[3];
    const float* W_v       = (const float*)d_in[4];
    const float* W_out     = (const float*)d_in[5];
    const float* b_out     = (const float*)d_in[6];
    const float* rotations = (const float*)d_in[7];
    float* out = (float*)d_out;

    dim3 gg(512 / 64, 16384 / 128);

    gemm_kernel<0><<<gg, 256>>>(queries, W_qk, nullptr, nullptr);
    gemm_kernel<1><<<gg, 256>>>(queries, W_v,  nullptr, nullptr);

    hash_sort_kernel<<<BHN * NH, 256>>>(rotations);

    cudaFuncSetAttribute(lsh_attn_kernel,
                         cudaFuncAttributeMaxDynamicSharedMemorySize, SMEM_ATTN);
    lsh_attn_kernel<<<BHN * 256, 256, SMEM_ATTN>>>();

    combine_kernel<<<(BHN * T * DH) / 256, 256>>>();

    gemm_kernel<2><<<gg, 256>>>(nullptr, W_out, b_out, out);
}